// round 13
// baseline (speedup 1.0000x reference)
#include <cuda_runtime.h>
#include <cuda_fp16.h>
#include <math.h>
#include <stdint.h>

#define BATCH 4
#define DIM   256
#define MID   128
#define HH    128
#define WW    128
#define EPSV  1e-5f

// ---------------- scratch (device globals; no runtime allocation) ----------
static const size_t SZ_MID = (size_t)BATCH * MID * HH * WW;   // 8,388,608
static const size_t SZ_DIM = (size_t)BATCH * DIM * HH * WW;   // 16,777,216

__device__ float g_relu1[SZ_MID];
__device__ float g_relu2[SZ_MID];
__device__ float g_y    [SZ_DIM];
__device__ float g_colmax[(size_t)BATCH * MID * WW];
__device__ float g_rowmax[(size_t)BATCH * MID * HH];
__device__ float g_U[(size_t)BATCH * 3 * DIM * WW];   // [b][hcase][co][w]
__device__ float g_V[(size_t)BATCH * 3 * DIM * HH];   // [b][wcase][co][h]
__device__ float g_scale[1024];
__device__ float g_shift[1024];
// half weights, layout [k][co][ci] (ci contiguous), 16B-aligned for uint4 IO
__device__ __align__(16) __half g_wt1 [9 * MID * DIM];    // p1  [9][128][256]
__device__ __align__(16) __half g_wt2 [9 * MID * DIM];    // p2
__device__ __align__(16) __half g_wtc1[DIM * DIM];        // skip 1x1 [1][256][256]
__device__ __align__(16) __half g_wtc2[9 * DIM * DIM];    // final

// ---------------- helpers ----------------------------------------------------
__device__ __forceinline__ void mma_f16(float* c, const uint32_t* a, const uint32_t* b) {
    asm volatile("mma.sync.aligned.m16n8k16.row.col.f32.f16.f16.f32 "
        "{%0,%1,%2,%3}, {%4,%5,%6,%7}, {%8,%9}, {%0,%1,%2,%3};"
        : "+f"(c[0]), "+f"(c[1]), "+f"(c[2]), "+f"(c[3])
        : "r"(a[0]), "r"(a[1]), "r"(a[2]), "r"(a[3]), "r"(b[0]), "r"(b[1]));
}

// row stride 20 words (40 halfs, 80B): bank = (20*row + word) mod 32 spans all
// 32 banks for every fragment access pattern.
#define STRW 20
#define A_TILE_W (128 * STRW)
#define B_TILE_W (130 * STRW)
#define SMEM_WORDS (3 * A_TILE_W + B_TILE_W)   // 10280 words = 41120 B

// ---------------- BN fold ---------------------------------------------------
__global__ void bnprep_kernel(const float* __restrict__ g, const float* __restrict__ b,
                              const float* __restrict__ m, const float* __restrict__ v,
                              float* __restrict__ sc, float* __restrict__ sh, int n)
{
    int i = blockIdx.x * blockDim.x + threadIdx.x;
    if (i < n) {
        float inv = rsqrtf(v[i] + EPSV);
        float s = g[i] * inv;
        sc[i] = s;
        sh[i] = b[i] - m[i] * s;
    }
}

// ------- weight transform: [CO,CI,KK] float -> [k][co][ci] half -------------
__global__ void wtrans_kernel(const float* __restrict__ w, __half* __restrict__ wt,
                              int COUT, int CIN, int KK)
{
    size_t n = (size_t)COUT * CIN * KK;
    for (size_t o = (size_t)blockIdx.x * blockDim.x + threadIdx.x; o < n;
         o += (size_t)gridDim.x * blockDim.x) {
        int ci = (int)(o % CIN);
        size_t t = o / CIN;
        int co = (int)(t % COUT);
        int k  = (int)(t / COUT);
        wt[o] = __float2half(w[((size_t)co * CIN + ci) * KK + k]);
    }
}

// --------- merge-conv separation: U[b][hcase][co][w], V[b][wcase][co][h] ----
// merge_conv(pool)[co,h,w] == U[case_h][co][w] + V[case_w][co][h] exactly
// (pool = cm[ci][w] + rm[ci][h]; zero-pad validity folds into tap subsets).
// p BN folded: scale into both, shift into V.
__global__ void ucompute_kernel(const float* __restrict__ pw,   // [256][128][3][3]
                                const float* __restrict__ cm,   // [b][ci][W]
                                const float* __restrict__ psc,
                                float* __restrict__ U)
{
    int idx = blockIdx.x * blockDim.x + threadIdx.x;
    if (idx >= BATCH * 3 * DIM * WW) return;
    const int w  = idx & 127;
    const int co = (idx >> 7) & 255;
    const int t  = idx >> 15;
    const int cs = t % 3;          // h-case: 0 -> h==0, 1 -> interior, 2 -> h==H-1
    const int b  = t / 3;
    const int dy0 = (cs == 0) ? 1 : 0;
    const int dy1 = (cs == 2) ? 1 : 2;
    float acc = 0.f;
    const float* cmb = cm + (size_t)b * MID * WW;
    for (int ci = 0; ci < MID; ci++) {
        const float* wp = pw + ((size_t)co * MID + ci) * 9;
        const float* cr = cmb + (size_t)ci * WW;
#pragma unroll
        for (int dx = 0; dx < 3; dx++) {
            const int wx = w + dx - 1;
            if (wx < 0 || wx >= WW) continue;
            float ws = 0.f;
            for (int dy = dy0; dy <= dy1; dy++) ws += wp[dy * 3 + dx];
            acc += ws * cr[wx];
        }
    }
    U[idx] = acc * psc[co];
}

__global__ void vcompute_kernel(const float* __restrict__ pw,
                                const float* __restrict__ rm,   // [b][ci][H]
                                const float* __restrict__ psc,
                                const float* __restrict__ psh,
                                float* __restrict__ V)
{
    int idx = blockIdx.x * blockDim.x + threadIdx.x;
    if (idx >= BATCH * 3 * DIM * HH) return;
    const int h  = idx & 127;
    const int co = (idx >> 7) & 255;
    const int t  = idx >> 15;
    const int cs = t % 3;          // w-case: 0 -> w==0, 1 -> interior, 2 -> w==W-1
    const int b  = t / 3;
    const int dx0 = (cs == 0) ? 1 : 0;
    const int dx1 = (cs == 2) ? 1 : 2;
    float acc = 0.f;
    const float* rmb = rm + (size_t)b * MID * HH;
    for (int ci = 0; ci < MID; ci++) {
        const float* wp = pw + ((size_t)co * MID + ci) * 9;
        const float* rr = rmb + (size_t)ci * HH;
#pragma unroll
        for (int dy = 0; dy < 3; dy++) {
            const int hy = h + dy - 1;
            if (hy < 0 || hy >= HH) continue;
            float ws = 0.f;
            for (int dx = dx0; dx <= dx1; dx++) ws += wp[dy * 3 + dx];
            acc += ws * rr[hy];
        }
    }
    V[idx] = acc * psc[co] + psh[co];
}

// ---------------- fp16 mma.sync implicit-GEMM conv --------------------------
// CTA: 128 co x 128 px (one output image row). 256 threads.
// Optional merge epilogue: out = relu(bn(acc) + U[ch][co][w] + V[cw][co][h]).
__global__ __launch_bounds__(256, 2)
void convmma_kernel(const float* __restrict__ in, int CIN,
                    const __half* __restrict__ wtT, int KK,     // 9 or 1
                    const float* __restrict__ scale,
                    const float* __restrict__ shift,
                    const float* __restrict__ mU,               // may be null
                    const float* __restrict__ mV,
                    float* __restrict__ out, int COUT, int do_relu)
{
    __shared__ __align__(16) uint32_t smw[SMEM_WORDS];
    uint32_t* sA = smw;                  // 3 tiles [128co][STRW]
    uint32_t* sB = smw + 3 * A_TILE_W;   // [130px][STRW], data rows 1..128

    const int tid  = threadIdx.x;
    const int wid  = tid >> 5;
    const int lane = tid & 31;
    const int y       = blockIdx.x;
    const int co_base = blockIdx.y * 128;
    const int b       = blockIdx.z;
    const int nCB  = CIN / 32;
    const int ndy  = (KK == 9) ? 3 : 1;
    const int ntap = (KK == 9) ? 3 : 1;

    const int wm = wid & 1;    // co half (64)
    const int wn = wid >> 1;   // px quarter (32)
    const int q  = lane >> 2;
    const int g  = lane & 3;

    // zero B pad rows (px_row 0 and 129), 40 words total
    if (tid < 2 * STRW) {
        const int r   = (tid < STRW) ? 0 : 129;
        const int col = (tid < STRW) ? tid : (tid - STRW);
        sB[r * STRW + col] = 0u;
    }

    float acc[4][4][4];
#pragma unroll
    for (int i = 0; i < 4; i++)
#pragma unroll
        for (int j = 0; j < 4; j++)
#pragma unroll
            for (int p = 0; p < 4; p++) acc[i][j][p] = 0.f;

    const size_t cstr = (size_t)HH * WW;

    for (int cb = 0; cb < nCB; cb++) {
        for (int idy = 0; idy < ndy; idy++) {
            const int yy = (KK == 9) ? (y + idy - 1) : y;
            if (yy < 0 || yy >= HH) continue;   // whole row contributes zero

            __syncthreads();   // previous unit fully consumed

            if (tid < 128) {
                // B: input row px=tid, 32 ci values -> 16 half2 words
                const int px = tid;
                const float* src = in + (((size_t)b * CIN + cb * 32) * HH + yy) * WW + px;
                uint32_t* dst = sB + (px + 1) * STRW;
#pragma unroll
                for (int c2 = 0; c2 < 16; c2++) {
                    float f0 = src[(size_t)(2 * c2)     * cstr];
                    float f1 = src[(size_t)(2 * c2 + 1) * cstr];
                    __half2 h = __floats2half2_rn(f0, f1);
                    dst[c2] = *(const uint32_t*)&h;
                }
            } else {
                // A: one co row (32 halfs = 4 x uint4) per tap
                const int u = tid - 128;   // co row 0..127
                for (int t3 = 0; t3 < ntap; t3++) {
                    const int k = (KK == 9) ? (idy * 3 + t3) : 0;
                    const __half* wr = wtT + ((size_t)k * COUT + co_base + u) * CIN + cb * 32;
                    const uint4 w0 = ((const uint4*)wr)[0];
                    const uint4 w1 = ((const uint4*)wr)[1];
                    const uint4 w2 = ((const uint4*)wr)[2];
                    const uint4 w3 = ((const uint4*)wr)[3];
                    uint4* dst = (uint4*)(sA + t3 * A_TILE_W + u * STRW);
                    dst[0] = w0;
                    dst[1] = w1;
                    dst[2] = w2;
                    dst[3] = w3;
                }
            }
            __syncthreads();

            // consume: ntap x 2 k-steps of m16n8k16
            for (int t3 = 0; t3 < ntap; t3++) {
                const uint32_t* tA = sA + t3 * A_TILE_W;
                const int bbase = (KK == 9) ? t3 : 1;   // px row offset (dx+1)
#pragma unroll
                for (int ks = 0; ks < 2; ks++) {
                    const int kw = ks * 8 + g;
                    uint32_t af[4][4], bf[4][2];
#pragma unroll
                    for (int mt = 0; mt < 4; mt++) {
                        const int r0 = wm * 64 + mt * 16 + q;
                        af[mt][0] = tA[r0 * STRW + kw];
                        af[mt][1] = tA[(r0 + 8) * STRW + kw];
                        af[mt][2] = tA[r0 * STRW + kw + 4];
                        af[mt][3] = tA[(r0 + 8) * STRW + kw + 4];
                    }
#pragma unroll
                    for (int nt = 0; nt < 4; nt++) {
                        const int pr = wn * 32 + nt * 8 + q + bbase;
                        bf[nt][0] = sB[pr * STRW + kw];
                        bf[nt][1] = sB[pr * STRW + kw + 4];
                    }
#pragma unroll
                    for (int mt = 0; mt < 4; mt++)
#pragma unroll
                        for (int nt = 0; nt < 4; nt++)
                            mma_f16(acc[mt][nt], af[mt], bf[nt]);
                }
            }
        }
    }

    // epilogue: BN (+merge broadcast U/V) (+relu), register write-out
    const int ch = (y == 0) ? 0 : ((y == HH - 1) ? 2 : 1);
#pragma unroll
    for (int mt = 0; mt < 4; mt++) {
        const int r0 = co_base + wm * 64 + mt * 16 + q;
        const int r1 = r0 + 8;
        const float sc0 = scale[r0], sh0 = shift[r0];
        const float sc1 = scale[r1], sh1 = shift[r1];
        const size_t ob0 = ((size_t)(b * COUT + r0) * HH + y) * WW;
        const size_t ob1 = ((size_t)(b * COUT + r1) * HH + y) * WW;
        const float* U0 = mU ? (mU + (((size_t)b * 3 + ch) * DIM + r0) * WW) : nullptr;
        const float* U1 = mU ? (mU + (((size_t)b * 3 + ch) * DIM + r1) * WW) : nullptr;
#pragma unroll
        for (int nt = 0; nt < 4; nt++) {
            const int c = wn * 32 + nt * 8 + 2 * g;
            float2 v0, v1;
            v0.x = acc[mt][nt][0] * sc0 + sh0;
            v0.y = acc[mt][nt][1] * sc0 + sh0;
            v1.x = acc[mt][nt][2] * sc1 + sh1;
            v1.y = acc[mt][nt][3] * sc1 + sh1;
            if (mU) {
                // c is even (never 127); c+1 is odd (never 0)
                const int cwx = (c == 0) ? 0 : 1;
                const int cwy = (c + 1 == WW - 1) ? 2 : 1;
                const float* Vb = mV + (size_t)b * 3 * DIM * HH;
                v0.x += U0[c]     + Vb[((size_t)cwx * DIM + r0) * HH + y];
                v0.y += U0[c + 1] + Vb[((size_t)cwy * DIM + r0) * HH + y];
                v1.x += U1[c]     + Vb[((size_t)cwx * DIM + r1) * HH + y];
                v1.y += U1[c + 1] + Vb[((size_t)cwy * DIM + r1) * HH + y];
            }
            if (do_relu) {
                v0.x = fmaxf(v0.x, 0.f); v0.y = fmaxf(v0.y, 0.f);
                v1.x = fmaxf(v1.x, 0.f); v1.y = fmaxf(v1.y, 0.f);
            }
            *(float2*)(out + ob0 + c) = v0;
            *(float2*)(out + ob1 + c) = v1;
        }
    }
}

// ---------------- pools: composed cummax pairs == global max broadcast ------
__global__ void colmax_kernel(const float* __restrict__ in, float* __restrict__ outv)
{
    int idx = blockIdx.x * blockDim.x + threadIdx.x;
    if (idx >= BATCH * MID * WW) return;
    int w  = idx % WW;
    int bc = idx / WW;
    const float* p = in + (size_t)bc * HH * WW + w;
    float m = -INFINITY;
#pragma unroll 4
    for (int h = 0; h < HH; h++) m = fmaxf(m, p[(size_t)h * WW]);
    outv[idx] = m;
}

__global__ void rowmax_kernel(const float* __restrict__ in, float* __restrict__ outv)
{
    int row  = blockIdx.x * (blockDim.x / 32) + (threadIdx.x >> 5);
    int lane = threadIdx.x & 31;
    if (row >= BATCH * MID * HH) return;
    const float* p = in + (size_t)row * WW;
    float m = -INFINITY;
    for (int w = lane; w < WW; w += 32) m = fmaxf(m, p[w]);
#pragma unroll
    for (int off = 16; off; off >>= 1) m = fmaxf(m, __shfl_xor_sync(0xFFFFFFFFu, m, off));
    if (lane == 0) outv[row] = m;
}

// ---------------- launch -----------------------------------------------------
extern "C" void kernel_launch(void* const* d_in, const int* in_sizes, int n_in,
                              void* d_out, int out_size)
{
    const float* x    = (const float*)d_in[0];
    const float* p1_w = (const float*)d_in[1];
    const float* p1_g = (const float*)d_in[2];
    const float* p1_b = (const float*)d_in[3];
    const float* p1_m = (const float*)d_in[4];
    const float* p1_v = (const float*)d_in[5];
    const float* p2_w = (const float*)d_in[6];
    const float* p2_g = (const float*)d_in[7];
    const float* p2_b = (const float*)d_in[8];
    const float* p2_m = (const float*)d_in[9];
    const float* p2_v = (const float*)d_in[10];
    const float* p_w  = (const float*)d_in[11];
    const float* p_g  = (const float*)d_in[12];
    const float* p_b  = (const float*)d_in[13];
    const float* p_m  = (const float*)d_in[14];
    const float* p_v  = (const float*)d_in[15];
    const float* c1_w = (const float*)d_in[16];
    const float* c1_g = (const float*)d_in[17];
    const float* c1_b = (const float*)d_in[18];
    const float* c1_m = (const float*)d_in[19];
    const float* c1_v = (const float*)d_in[20];
    const float* c2_w = (const float*)d_in[21];
    const float* c2_g = (const float*)d_in[22];
    const float* c2_b = (const float*)d_in[23];
    const float* c2_m = (const float*)d_in[24];
    const float* c2_v = (const float*)d_in[25];

    float *relu1, *relu2, *y, *colm, *rowm, *U, *V, *sc, *sh;
    __half *wt1, *wt2, *wtc1, *wtc2;
    cudaGetSymbolAddress((void**)&relu1, g_relu1);
    cudaGetSymbolAddress((void**)&relu2, g_relu2);
    cudaGetSymbolAddress((void**)&y,     g_y);
    cudaGetSymbolAddress((void**)&colm,  g_colmax);
    cudaGetSymbolAddress((void**)&rowm,  g_rowmax);
    cudaGetSymbolAddress((void**)&U,     g_U);
    cudaGetSymbolAddress((void**)&V,     g_V);
    cudaGetSymbolAddress((void**)&sc,    g_scale);
    cudaGetSymbolAddress((void**)&sh,    g_shift);
    cudaGetSymbolAddress((void**)&wt1,   g_wt1);
    cudaGetSymbolAddress((void**)&wt2,   g_wt2);
    cudaGetSymbolAddress((void**)&wtc1,  g_wtc1);
    cudaGetSymbolAddress((void**)&wtc2,  g_wtc2);

    // BN folds: offsets p1:0, p2:128, p:256, c1:512, c2:768
    bnprep_kernel<<<1, 128>>>(p1_g, p1_b, p1_m, p1_v, sc + 0,   sh + 0,   MID);
    bnprep_kernel<<<1, 128>>>(p2_g, p2_b, p2_m, p2_v, sc + 128, sh + 128, MID);
    bnprep_kernel<<<1, 256>>>(p_g,  p_b,  p_m,  p_v,  sc + 256, sh + 256, DIM);
    bnprep_kernel<<<1, 256>>>(c1_g, c1_b, c1_m, c1_v, sc + 512, sh + 512, DIM);
    bnprep_kernel<<<1, 256>>>(c2_g, c2_b, c2_m, c2_v, sc + 768, sh + 768, DIM);

    // weight transforms -> [k][co][ci] half (merge conv no longer needs one)
    wtrans_kernel<<<512, 256>>>(p1_w, wt1,  MID, DIM, 9);
    wtrans_kernel<<<512, 256>>>(p2_w, wt2,  MID, DIM, 9);
    wtrans_kernel<<<256, 256>>>(c1_w, wtc1, DIM, DIM, 1);
    wtrans_kernel<<<1024, 256>>>(c2_w, wtc2, DIM, DIM, 9);

    dim3 blk(256);
    dim3 g_mid(HH, MID / 128, BATCH);   // (128, 1, 4)
    dim3 g_dim(HH, DIM / 128, BATCH);   // (128, 2, 4)

    // branch convs (fp16 mma.sync, fp32 accumulate)
    convmma_kernel<<<g_mid, blk>>>(x, DIM, wt1, 9, sc + 0,   sh + 0,   nullptr, nullptr, relu1, MID, 1);
    convmma_kernel<<<g_mid, blk>>>(x, DIM, wt2, 9, sc + 128, sh + 128, nullptr, nullptr, relu2, MID, 1);

    // composed directional pools == global max along H / W
    colmax_kernel<<<(BATCH * MID * WW + 255) / 256, 256>>>(relu1, colm);
    rowmax_kernel<<<(BATCH * MID * HH) / 8, 256>>>(relu2, rowm);

    // merge conv separated into 1-D U/V terms (exact, incl. zero-pad cases)
    ucompute_kernel<<<(BATCH * 3 * DIM * WW + 255) / 256, 256>>>(p_w, colm, sc + 256, U);
    vcompute_kernel<<<(BATCH * 3 * DIM * HH + 255) / 256, 256>>>(p_w, rowm, sc + 256, sh + 256, V);

    // c1 1x1 conv + BN, fused with merge broadcast + residual relu -> y
    convmma_kernel<<<g_dim, blk>>>(x, DIM, wtc1, 1, sc + 512, sh + 512, U, V, y, DIM, 1);

    // final conv + BN + ReLU -> output
    convmma_kernel<<<g_dim, blk>>>(y, DIM, wtc2, 9, sc + 768, sh + 768, nullptr, nullptr, (float*)d_out, DIM, 1);
}